// round 12
// baseline (speedup 1.0000x reference)
#include <cuda_runtime.h>
#include <cuda_fp16.h>
#include <cstdint>

// ============================================================================
// HardMemory R12: K-halved fp16 HMMA screen (Cauchy-Schwarz), 1024 threads.
//   x: [32, 512, 64, 64] f32, memory: [1024, 512] f32, out like x.
// cos(x, m_hat) <= (dot1(x1,m1_hat) + ||x2||*Bmax)/||x||, Bmax = max ||m2_hat||.
// GEMM K=256 only; flag iff dot1max + ||x2||*Bmax > 0.75*||x|| (true 0.8).
// Flagged pixels (expected none) -> exact fp32 path (also true argmax).
// R12 vs R11: 32 warps (8/SMSP, occ 50%) to fix the latency-bound profile
// (R11: tensor 36%, L1 29%, issue 22% -> nothing saturated). Warp tile
// m64xn32 so accumulators fit the 64-reg/thread cap at 1024 threads.
// ============================================================================

#define THRESH   0.8f
#define CDIM     512
#define KGEMM    256
#define HWDIM    4096
#define MMEM     1024
#define TILE_PX  128
#define THREADS  1024

// Prepass: normalized memory rows, first 256 channels, fp16 [1024][256]
__device__ __align__(16) unsigned char g_memh[MMEM * KGEMM * 2];
__device__ float g_bmax;   // max over rows of ||m_hat[256:512]|| (zero-init)

// ---------------------------------------------------------------------------
// smem layout (bytes)
// ---------------------------------------------------------------------------
#define SM_X     0                        // [256 k][256B px-fp16] = 65536
#define SM_B     65536                    // 2 x [512 m][128B k-fp16] = 131072
#define SM_N2    (SM_B + 131072)          // 128 f32 full ||x||^2
#define SM_T2    (SM_N2 + 512)            // 128 f32 tail ||x2||^2
#define SM_RM    (SM_T2 + 512)            // 8*128 f32
#define SM_FLAG  (SM_RM + 4096)           // 128 i32
#define SM_PASS  (SM_FLAG + 512)
#define SM_IDX   (SM_PASS + 512)
#define SM_XV    (SM_IDX + 512)           // 512 f32
#define SM_BESTU (SM_XV + 2048)
#define SM_BESTI (SM_BESTU + 4)
#define SM_TOTAL (SM_BESTI + 60)

// ---------------------------------------------------------------------------
__device__ __forceinline__ uint32_t smem_u32(const void* p) {
    uint32_t a;
    asm("{ .reg .u64 t; cvta.to.shared.u64 t, %1; cvt.u32.u64 %0, t; }"
        : "=r"(a) : "l"(p));
    return a;
}
__device__ __forceinline__ void cp_async16(uint32_t dst, const void* src) {
    asm volatile("cp.async.cg.shared.global [%0], [%1], 16;"
                 :: "r"(dst), "l"(src) : "memory");
}
#define CP_COMMIT() asm volatile("cp.async.commit_group;" ::: "memory")
#define CP_WAIT(N)  asm volatile("cp.async.wait_group %0;" :: "n"(N) : "memory")

__device__ __forceinline__ void ldsm_x4(uint32_t& r0, uint32_t& r1,
                                        uint32_t& r2, uint32_t& r3, uint32_t a) {
    asm volatile("ldmatrix.sync.aligned.m8n8.x4.shared.b16 {%0,%1,%2,%3}, [%4];"
                 : "=r"(r0), "=r"(r1), "=r"(r2), "=r"(r3) : "r"(a));
}
__device__ __forceinline__ void ldsm_x4t(uint32_t& r0, uint32_t& r1,
                                         uint32_t& r2, uint32_t& r3, uint32_t a) {
    asm volatile("ldmatrix.sync.aligned.m8n8.x4.trans.shared.b16 {%0,%1,%2,%3}, [%4];"
                 : "=r"(r0), "=r"(r1), "=r"(r2), "=r"(r3) : "r"(a));
}
__device__ __forceinline__ void mma_h(uint32_t& d0, uint32_t& d1,
                                      uint32_t a0, uint32_t a1, uint32_t a2, uint32_t a3,
                                      uint32_t b0, uint32_t b1) {
    asm volatile(
        "mma.sync.aligned.m16n8k16.row.col.f16.f16.f16.f16 "
        "{%0,%1}, {%2,%3,%4,%5}, {%6,%7}, {%0,%1};"
        : "+r"(d0), "+r"(d1)
        : "r"(a0), "r"(a1), "r"(a2), "r"(a3), "r"(b0), "r"(b1));
}
__device__ __forceinline__ uint32_t hmax2u(uint32_t a, uint32_t b) {
    const __half2 r = __hmax2(*(const __half2*)&a, *(const __half2*)&b);
    return *(const uint32_t*)&r;
}

// ---------------------------------------------------------------------------
// Prepass: m_hat = memory/max(||row||,eps); store m_hat[0:256] fp16;
// atomicMax ||m_hat[256:512]|| into g_bmax (idempotent across graph replays).
// ---------------------------------------------------------------------------
__global__ __launch_bounds__(128) void normalize_mem_kernel(const float* __restrict__ memory) {
    const int m = blockIdx.x, tid = threadIdx.x;
    const float4 v = *(const float4*)(memory + (size_t)m * CDIM + tid * 4);
    float ss = v.x * v.x + v.y * v.y + v.z * v.z + v.w * v.w;
    #pragma unroll
    for (int o = 16; o > 0; o >>= 1) ss += __shfl_xor_sync(0xffffffffu, ss, o);
    __shared__ float ws[4];
    if ((tid & 31) == 0) ws[tid >> 5] = ss;
    __syncthreads();
    const float tot  = ws[0] + ws[1] + ws[2] + ws[3];
    const float tail = ws[2] + ws[3];                 // k in [256, 512)
    const float s = 1.0f / fmaxf(sqrtf(tot), 1e-12f);
    if (tid < 64) {                                   // k < 256: store fp16
        uint32_t p0 = __half_as_ushort(__float2half_rn(v.x * s)) |
                      ((uint32_t)__half_as_ushort(__float2half_rn(v.y * s)) << 16);
        uint32_t p1 = __half_as_ushort(__float2half_rn(v.z * s)) |
                      ((uint32_t)__half_as_ushort(__float2half_rn(v.w * s)) << 16);
        *(uint2*)(g_memh + (size_t)m * (KGEMM * 2) + tid * 8) = make_uint2(p0, p1);
    }
    if (tid == 0) {
        const float tn = sqrtf(tail) * s;             // ||m_hat tail|| (>= 0)
        atomicMax((unsigned*)&g_bmax, __float_as_uint(tn));
    }
}

// ---------------------------------------------------------------------------
// Main: 1024 CTAs x 1024 thr. 32 warps = 8 warp_m (m64) x 4 warp_n (n32).
// Chunk = 512 mem rows (2 chunks). B slices [512 m][64 k] fp16 = 64KB, x2 buf.
// ---------------------------------------------------------------------------
__global__ __launch_bounds__(THREADS, 1) void hardmem_main_kernel(
    const float* __restrict__ x,
    const float* __restrict__ memory,
    float* __restrict__ out)
{
    extern __shared__ char smem[];
    const uint32_t smx = smem_u32(smem);
    const int tid = threadIdx.x;
    const int lane = tid & 31;
    const int wid = tid >> 5;
    const int warp_m = wid >> 2;        // 0..7 -> m64 within 512-chunk
    const int warp_n = wid & 3;         // 0..3 -> px32
    const int b  = blockIdx.x >> 5;
    const int n0 = (blockIdx.x & 31) << 7;

    float* s_n2   = (float*)(smem + SM_N2);
    float* s_t2   = (float*)(smem + SM_T2);
    float* s_rm   = (float*)(smem + SM_RM);
    int*   s_flag = (int*)(smem + SM_FLAG);
    int*   s_pass = (int*)(smem + SM_PASS);
    int*   s_idx  = (int*)(smem + SM_IDX);
    float* s_xv   = (float*)(smem + SM_XV);
    unsigned* s_bestu = (unsigned*)(smem + SM_BESTU);
    int*      s_besti = (int*)(smem + SM_BESTI);

    if (tid < TILE_PX) { s_n2[tid] = 0.0f; s_t2[tid] = 0.0f; }

    // ---- prefetch B slice 0 (chunk 0, k 0..63): 512 rows x 128B ----
    {
        #pragma unroll
        for (int i = 0; i < 4; ++i) {
            const int j = tid + i * THREADS;          // 4096 granules
            const int m = j >> 3, g = j & 7;
            cp_async16(smx + SM_B + m * 128 + (((uint32_t)g ^ (uint32_t)(m & 7)) << 4),
                       g_memh + (size_t)m * 512 + (size_t)g * 16);
        }
        CP_COMMIT();
    }

    // ---- x prologue: single pass. k<256: store fp16 + head norm;
    //      k>=256: tail norm only. Per-lane fixed 4 pixels. ----
    {
        const float* xb = x + (size_t)b * CDIM * HWDIM + n0;
        const int px4 = lane << 2;
        float a1[4] = {0.f, 0.f, 0.f, 0.f};
        float a2[4] = {0.f, 0.f, 0.f, 0.f};
        #pragma unroll 4
        for (int it = 0; it < 8; ++it) {              // k in [0,256)
            const int k = wid + it * 32;
            const float4 v = *(const float4*)(xb + (size_t)k * HWDIM + px4);
            a1[0] += v.x * v.x; a1[1] += v.y * v.y;
            a1[2] += v.z * v.z; a1[3] += v.w * v.w;
            uint32_t p0 = __half_as_ushort(__float2half_rn(v.x)) |
                          ((uint32_t)__half_as_ushort(__float2half_rn(v.y)) << 16);
            uint32_t p1 = __half_as_ushort(__float2half_rn(v.z)) |
                          ((uint32_t)__half_as_ushort(__float2half_rn(v.w)) << 16);
            const uint32_t a = (uint32_t)(k << 8) + (((uint32_t)(px4 << 1)) ^ ((k & 7) << 4));
            *(uint2*)(smem + SM_X + a) = make_uint2(p0, p1);
        }
        #pragma unroll 4
        for (int it = 8; it < 16; ++it) {             // k in [256,512)
            const int k = wid + it * 32;
            const float4 v = *(const float4*)(xb + (size_t)k * HWDIM + px4);
            a2[0] += v.x * v.x; a2[1] += v.y * v.y;
            a2[2] += v.z * v.z; a2[3] += v.w * v.w;
        }
        #pragma unroll
        for (int j = 0; j < 4; ++j) {
            atomicAdd(&s_n2[px4 + j], a1[j] + a2[j]);
            atomicAdd(&s_t2[px4 + j], a2[j]);
        }
    }

    // ---- lane addressing ----
    const int lr = lane & 7;
    const int lh = (lane >> 3) & 1;
    const int lq = (lane >> 4) & 1;
    const uint32_t a_hi = (uint32_t)(lane >> 4);
    // A rows: warp_m*64 + mt*16 + (lane&15); (row & 7) == (lane & 7) for all mt
    const uint32_t aB0 = (uint32_t)((warp_m * 64 + (lane & 15)) << 7);  // *128B
    const uint32_t fA  = (uint32_t)lr;
    const uint32_t krow = (uint32_t)(lr + lh * 8);
    uint32_t pxoff[2];
    #pragma unroll
    for (int G = 0; G < 2; ++G)
        pxoff[G] = ((uint32_t)((warp_n * 32 + lq * 8 + G * 16) << 1)) ^ ((uint32_t)lr << 4);

    uint32_t rmax2[4];
    {
        const __half2 ninf = __float2half2_rn(-60000.0f);
        #pragma unroll
        for (int s = 0; s < 4; ++s) rmax2[s] = *(const uint32_t*)&ninf;
    }
    uint32_t d[4][4][2];                 // [mt][nt][reg] fp16x2 accum (32 regs)

    // ---- mainloop: 8 slices = 2 chunks x 4 k-slices of 64 ----
    #pragma unroll 1
    for (int ts = 0; ts < 8; ++ts) {
        if (ts + 1 < 8) {
            const int nx2 = ts + 1;
            const unsigned char* src = g_memh +
                (size_t)(nx2 >> 2) * (512 * 512) + (size_t)(nx2 & 3) * 128;
            const uint32_t dstb = smx + SM_B + (nx2 & 1) * 65536;
            #pragma unroll
            for (int i = 0; i < 4; ++i) {
                const int j = tid + i * THREADS;
                const int m = j >> 3, g = j & 7;
                cp_async16(dstb + m * 128 + (((uint32_t)g ^ (uint32_t)(m & 7)) << 4),
                           src + (size_t)m * 512 + (size_t)g * 16);
            }
            CP_COMMIT();
            CP_WAIT(1);
        } else {
            CP_WAIT(0);
        }
        __syncthreads();

        if ((ts & 3) == 0) {
            #pragma unroll
            for (int mt = 0; mt < 4; ++mt)
                #pragma unroll
                for (int nt = 0; nt < 4; ++nt)
                    d[mt][nt][0] = d[mt][nt][1] = 0u;
        }

        const uint32_t abuf = smx + SM_B + (ts & 1) * 65536;
        const uint32_t kbase = (uint32_t)((ts & 3) * 64);

        #pragma unroll
        for (int ks = 0; ks < 4; ++ks) {
            // B first (reused by all 4 mt), then per-mt A (only 4 regs live)
            uint32_t bq[2][4];
            const uint32_t brow = smx + SM_X + ((kbase + (uint32_t)(ks * 16) + krow) << 8);
            #pragma unroll
            for (int G = 0; G < 2; ++G)
                ldsm_x4t(bq[G][0], bq[G][1], bq[G][2], bq[G][3], brow + pxoff[G]);
            #pragma unroll
            for (int mt = 0; mt < 4; ++mt) {
                uint32_t a0, a1, a2, a3;
                ldsm_x4(a0, a1, a2, a3,
                        abuf + aB0 + (uint32_t)(mt * 2048) +
                        (((((uint32_t)ks << 1) | a_hi) ^ fA) << 4));
                #pragma unroll
                for (int nt = 0; nt < 4; ++nt)
                    mma_h(d[mt][nt][0], d[mt][nt][1], a0, a1, a2, a3,
                          bq[nt >> 1][(nt & 1) * 2], bq[nt >> 1][(nt & 1) * 2 + 1]);
            }
        }

        if ((ts & 3) == 3) {             // chunk done: pure max fold (no idx)
            #pragma unroll
            for (int nt = 0; nt < 4; ++nt)
                #pragma unroll
                for (int mt = 0; mt < 4; ++mt)
                    rmax2[nt] = hmax2u(rmax2[nt], hmax2u(d[mt][nt][0], d[mt][nt][1]));
        }
        __syncthreads();
    }

    // ---- cross-lane max (rows live on lane>>2) ----
    #pragma unroll
    for (int o = 4; o <= 16; o <<= 1)
        #pragma unroll
        for (int s = 0; s < 4; ++s)
            rmax2[s] = hmax2u(rmax2[s], __shfl_xor_sync(0xffffffffu, rmax2[s], o));
    if (lane < 4) {
        #pragma unroll
        for (int nt = 0; nt < 4; ++nt) {
            const float2 f = __half22float2(*(const __half2*)&rmax2[nt]);
            const int px = warp_n * 32 + (nt >> 1) * 16 + (nt & 1) * 8 + lane * 2;
            s_rm[warp_m * 128 + px]     = f.x;
            s_rm[warp_m * 128 + px + 1] = f.y;
        }
    }
    __syncthreads();

    // ---- per-pixel screen: dot1max + ||x2||*Bmax > 0.75*||x|| ? ----
    const float bmax = g_bmax;
    if (tid < TILE_PX) {
        float bv = s_rm[tid];
        #pragma unroll
        for (int g = 1; g < 8; ++g) bv = fmaxf(bv, s_rm[g * 128 + tid]);
        const float nx = fmaxf(sqrtf(s_n2[tid]), 1e-12f);
        const float xt = sqrtf(s_t2[tid]);
        s_flag[tid] = (bv + xt * bmax > 0.75f * nx) ? 1 : 0;
        s_pass[tid] = 0;
        s_idx[tid]  = 0;
    }
    __syncthreads();

    // ---- exact fp32 path for flagged pixels (expected: none) ----
    for (int px = 0; px < TILE_PX; ++px) {
        if (!s_flag[px]) continue;
        for (int c = tid; c < CDIM; c += THREADS)
            s_xv[c] = x[(size_t)b * CDIM * HWDIM + (size_t)c * HWDIM + n0 + px];
        if (tid == 0) { *s_bestu = 0u; *s_besti = 0x7fffffff; }
        __syncthreads();
        {
            const int mm = tid;                       // 1 row per thread
            const float* mr = memory + (size_t)mm * CDIM;
            float dot = 0.f, nn = 0.f;
            for (int c = 0; c < CDIM; ++c) { const float mv = mr[c]; dot += s_xv[c] * mv; nn += mv * mv; }
            const float v = dot / fmaxf(sqrtf(nn), 1e-12f);
            unsigned enc = __float_as_uint(v);
            enc = (enc & 0x80000000u) ? ~enc : (enc | 0x80000000u);
            atomicMax(s_bestu, enc);
            __syncthreads();
            if (enc == *s_bestu) atomicMin(s_besti, mm);
        }
        __syncthreads();
        if (tid == 0) {
            unsigned u = *s_bestu;
            const float bvf = __uint_as_float((u & 0x80000000u) ? (u & 0x7fffffffu) : ~u);
            const float nx = fmaxf(sqrtf(s_n2[px]), 1e-12f);
            s_pass[px] = (bvf > THRESH * nx) ? 1 : 0;
            s_idx[px]  = *s_besti;
        }
        __syncthreads();
    }
    __syncthreads();

    // ---- writeback: full tile, coalesced; skip gather loads when masked ----
    {
        const int pxl = tid & 127;
        const int c0  = tid >> 7;                     // 0..7
        float* ob = out + (size_t)b * CDIM * HWDIM + n0 + pxl;
        if (s_pass[pxl]) {
            const float* mrow = memory + (size_t)s_idx[pxl] * CDIM;
            #pragma unroll 8
            for (int c = c0; c < CDIM; c += 8)
                ob[(size_t)c * HWDIM] = mrow[c];
        } else {
            #pragma unroll 8
            for (int c = c0; c < CDIM; c += 8)
                ob[(size_t)c * HWDIM] = 0.0f;
        }
    }
}

// ---------------------------------------------------------------------------
extern "C" void kernel_launch(void* const* d_in, const int* in_sizes, int n_in,
                              void* d_out, int out_size) {
    const float* x      = (const float*)d_in[0];
    const float* memory = (const float*)d_in[1];
    float* out          = (float*)d_out;

    cudaFuncSetAttribute(hardmem_main_kernel,
                         cudaFuncAttributeMaxDynamicSharedMemorySize, SM_TOTAL);

    normalize_mem_kernel<<<MMEM, 128>>>(memory);
    hardmem_main_kernel<<<32 * (HWDIM / TILE_PX), THREADS, SM_TOTAL>>>(x, memory, out);
}

// round 13
// speedup vs baseline: 1.8022x; 1.8022x over previous
#include <cuda_runtime.h>
#include <cuda_fp16.h>
#include <cstdint>

// ============================================================================
// HardMemory R13: K-halved fp16 HMMA screen (Cauchy-Schwarz), 512 threads,
// x-load overlapped into mainloop + frag double-buffered ks pipeline.
//   x: [32, 512, 64, 64] f32, memory: [1024, 512] f32, out like x.
// cos(x, m_hat) <= (dot1(x1,m1_hat) + ||x2||*Bmax)/||x||, Bmax = max ||m2_hat||.
// GEMM K=256 only; flag iff dot1max + ||x2||*Bmax > 0.75*||x|| (true 0.8).
// Flagged pixels (expected none) -> exact fp32 path (also true argmax).
// R12 lesson: >512 resident threads => 64-reg cap => RF bank conflicts on
// HMMA operands (tensor-active +57%). Stay at 512 thr / 128 regs.
// ============================================================================

#define THRESH   0.8f
#define CDIM     512
#define KGEMM    256
#define HWDIM    4096
#define MMEM     1024
#define TILE_PX  128
#define THREADS  512

// Prepass: normalized memory rows, first 256 channels, fp16 [1024][256]
__device__ __align__(16) unsigned char g_memh[MMEM * KGEMM * 2];
__device__ float g_bmax;   // max over rows of ||m_hat[256:512]|| (zero-init)

// ---------------------------------------------------------------------------
// smem layout (bytes)
// ---------------------------------------------------------------------------
#define SM_X     0                        // [256 k][256B px-fp16] = 65536
#define SM_B     65536                    // 2 x [256 m][256B k-fp16] = 131072
#define SM_N2    196608                   // 128 f32 full ||x||^2
#define SM_T2    197120                   // 128 f32 tail ||x2||^2
#define SM_RM    197632                   // 4*128 f32
#define SM_FLAG  199680                   // 128 i32
#define SM_PASS  200192
#define SM_IDX   200704
#define SM_XV    201216                   // 512 f32
#define SM_BESTU 203264
#define SM_BESTI 203268
#define SM_TOTAL 203328

// ---------------------------------------------------------------------------
__device__ __forceinline__ uint32_t smem_u32(const void* p) {
    uint32_t a;
    asm("{ .reg .u64 t; cvta.to.shared.u64 t, %1; cvt.u32.u64 %0, t; }"
        : "=r"(a) : "l"(p));
    return a;
}
__device__ __forceinline__ void cp_async16(uint32_t dst, const void* src) {
    asm volatile("cp.async.cg.shared.global [%0], [%1], 16;"
                 :: "r"(dst), "l"(src) : "memory");
}
#define CP_COMMIT() asm volatile("cp.async.commit_group;" ::: "memory")
#define CP_WAIT(N)  asm volatile("cp.async.wait_group %0;" :: "n"(N) : "memory")

__device__ __forceinline__ void ldsm_x4(uint32_t& r0, uint32_t& r1,
                                        uint32_t& r2, uint32_t& r3, uint32_t a) {
    asm volatile("ldmatrix.sync.aligned.m8n8.x4.shared.b16 {%0,%1,%2,%3}, [%4];"
                 : "=r"(r0), "=r"(r1), "=r"(r2), "=r"(r3) : "r"(a));
}
__device__ __forceinline__ void ldsm_x4t(uint32_t& r0, uint32_t& r1,
                                         uint32_t& r2, uint32_t& r3, uint32_t a) {
    asm volatile("ldmatrix.sync.aligned.m8n8.x4.trans.shared.b16 {%0,%1,%2,%3}, [%4];"
                 : "=r"(r0), "=r"(r1), "=r"(r2), "=r"(r3) : "r"(a));
}
__device__ __forceinline__ void mma_h(uint32_t& d0, uint32_t& d1,
                                      uint32_t a0, uint32_t a1, uint32_t a2, uint32_t a3,
                                      uint32_t b0, uint32_t b1) {
    asm volatile(
        "mma.sync.aligned.m16n8k16.row.col.f16.f16.f16.f16 "
        "{%0,%1}, {%2,%3,%4,%5}, {%6,%7}, {%0,%1};"
        : "+r"(d0), "+r"(d1)
        : "r"(a0), "r"(a1), "r"(a2), "r"(a3), "r"(b0), "r"(b1));
}
__device__ __forceinline__ uint32_t hmax2u(uint32_t a, uint32_t b) {
    const __half2 r = __hmax2(*(const __half2*)&a, *(const __half2*)&b);
    return *(const uint32_t*)&r;
}

// ---------------------------------------------------------------------------
// Prepass: m_hat = memory/max(||row||,eps); store m_hat[0:256] fp16;
// atomicMax ||m_hat[256:512]|| into g_bmax (idempotent across graph replays).
// ---------------------------------------------------------------------------
__global__ __launch_bounds__(128) void normalize_mem_kernel(const float* __restrict__ memory) {
    const int m = blockIdx.x, tid = threadIdx.x;
    const float4 v = *(const float4*)(memory + (size_t)m * CDIM + tid * 4);
    float ss = v.x * v.x + v.y * v.y + v.z * v.z + v.w * v.w;
    #pragma unroll
    for (int o = 16; o > 0; o >>= 1) ss += __shfl_xor_sync(0xffffffffu, ss, o);
    __shared__ float ws[4];
    if ((tid & 31) == 0) ws[tid >> 5] = ss;
    __syncthreads();
    const float tot  = ws[0] + ws[1] + ws[2] + ws[3];
    const float tail = ws[2] + ws[3];                 // k in [256, 512)
    const float s = 1.0f / fmaxf(sqrtf(tot), 1e-12f);
    if (tid < 64) {                                   // k < 256: store fp16
        uint32_t p0 = __half_as_ushort(__float2half_rn(v.x * s)) |
                      ((uint32_t)__half_as_ushort(__float2half_rn(v.y * s)) << 16);
        uint32_t p1 = __half_as_ushort(__float2half_rn(v.z * s)) |
                      ((uint32_t)__half_as_ushort(__float2half_rn(v.w * s)) << 16);
        *(uint2*)(g_memh + (size_t)m * (KGEMM * 2) + tid * 8) = make_uint2(p0, p1);
    }
    if (tid == 0) {
        const float tn = sqrtf(tail) * s;             // ||m_hat tail|| (>= 0)
        atomicMax((unsigned*)&g_bmax, __float_as_uint(tn));
    }
}

// ---------------------------------------------------------------------------
// Main: 1024 CTAs x 512 thr. 16 warps = 4 warp_m (m64) x 4 warp_n (n32).
// Chunk = 256 mem rows (4 chunks); B slice [256 m][128 k] fp16 = 64KB, x2 buf.
// 8 slices; x head k[128,256) loaded during slice 0; tail norms spread over
// all 8 slices; A/B frags double-buffered across ks.
// ---------------------------------------------------------------------------
__global__ __launch_bounds__(THREADS, 1) void hardmem_main_kernel(
    const float* __restrict__ x,
    const float* __restrict__ memory,
    float* __restrict__ out)
{
    extern __shared__ char smem[];
    const uint32_t smx = smem_u32(smem);
    const int tid = threadIdx.x;
    const int lane = tid & 31;
    const int wid = tid >> 5;
    const int warp_m = wid >> 2;        // 0..3 -> m64 within 256-chunk
    const int warp_n = wid & 3;         // 0..3 -> px32
    const int b  = blockIdx.x >> 5;
    const int n0 = (blockIdx.x & 31) << 7;

    float* s_n2   = (float*)(smem + SM_N2);
    float* s_t2   = (float*)(smem + SM_T2);
    float* s_rm   = (float*)(smem + SM_RM);
    int*   s_flag = (int*)(smem + SM_FLAG);
    int*   s_pass = (int*)(smem + SM_PASS);
    int*   s_idx  = (int*)(smem + SM_IDX);
    float* s_xv   = (float*)(smem + SM_XV);
    unsigned* s_bestu = (unsigned*)(smem + SM_BESTU);
    int*      s_besti = (int*)(smem + SM_BESTI);

    if (tid < TILE_PX) { s_n2[tid] = 0.0f; s_t2[tid] = 0.0f; }

    const float* xb = x + (size_t)b * CDIM * HWDIM + n0;
    const int px4 = lane << 2;                 // 4 fixed pixels per lane
    float a1[4] = {0.f, 0.f, 0.f, 0.f};        // head ||x1||^2 partials
    float a2[4] = {0.f, 0.f, 0.f, 0.f};        // tail ||x2||^2 partials

    // ---- prefetch B slice 0 (chunk 0, k 0..127): 256 rows x 256B = 64KB ----
    {
        #pragma unroll
        for (int i = 0; i < 8; ++i) {
            const int j = tid + i * THREADS;          // 4096 granules of 16B
            const int m = j >> 4, g = j & 15;
            cp_async16(smx + SM_B + m * 256 + (((uint32_t)g ^ (uint32_t)(m & 7)) << 4),
                       g_memh + (size_t)m * 512 + (size_t)g * 16);
        }
        CP_COMMIT();
    }

    // ---- serial head: X k in [0,128) only (rest overlapped in mainloop) ----
    {
        #pragma unroll 4
        for (int it = 0; it < 8; ++it) {
            const int k = wid + it * 16;
            const float4 v = *(const float4*)(xb + (size_t)k * HWDIM + px4);
            a1[0] += v.x * v.x; a1[1] += v.y * v.y;
            a1[2] += v.z * v.z; a1[3] += v.w * v.w;
            uint32_t p0 = __half_as_ushort(__float2half_rn(v.x)) |
                          ((uint32_t)__half_as_ushort(__float2half_rn(v.y)) << 16);
            uint32_t p1 = __half_as_ushort(__float2half_rn(v.z)) |
                          ((uint32_t)__half_as_ushort(__float2half_rn(v.w)) << 16);
            const uint32_t a = (uint32_t)(k << 8) + (((uint32_t)(px4 << 1)) ^ ((k & 7) << 4));
            *(uint2*)(smem + SM_X + a) = make_uint2(p0, p1);
        }
    }

    // ---- lane addressing ----
    const int lr = lane & 7;
    const int lh = (lane >> 3) & 1;
    const int lq = (lane >> 4) & 1;
    const uint32_t a_hi = (uint32_t)(lane >> 4);
    // A rows: warp_m*64 + mt*16 + (lane&15); (row&7)==(lane&7) for all mt
    const uint32_t aB0 = (uint32_t)((warp_m * 64 + (lane & 15)) << 8);  // *256B
    const uint32_t fA  = (uint32_t)lr;
    const uint32_t krow = (uint32_t)(lr + lh * 8);
    uint32_t pxoff[2];
    #pragma unroll
    for (int G = 0; G < 2; ++G)
        pxoff[G] = ((uint32_t)((warp_n * 32 + lq * 8 + G * 16) << 1)) ^ ((uint32_t)lr << 4);

    uint32_t rmax2[4];
    {
        const __half2 ninf = __float2half2_rn(-60000.0f);
        #pragma unroll
        for (int s = 0; s < 4; ++s) rmax2[s] = *(const uint32_t*)&ninf;
    }
    uint32_t d[4][4][2];                 // [mt][nt][reg] fp16x2 accum (32 regs)
    uint32_t fa[2][16], fb[2][8];        // double-buffered frags (48 regs)

    // ---- mainloop: 8 slices = 4 chunks x 2 k-slices of 128 ----
    #pragma unroll 1
    for (int ts = 0; ts < 8; ++ts) {
        if (ts + 1 < 8) {
            const int nx2 = ts + 1;
            const unsigned char* src = g_memh +
                (size_t)(nx2 >> 1) * (256 * 512) + (size_t)(nx2 & 1) * 256;
            const uint32_t dstb = smx + SM_B + (nx2 & 1) * 65536;
            #pragma unroll
            for (int i = 0; i < 8; ++i) {
                const int j = tid + i * THREADS;
                const int m = j >> 4, g = j & 15;
                cp_async16(dstb + m * 256 + (((uint32_t)g ^ (uint32_t)(m & 7)) << 4),
                           src + (size_t)m * 512 + (size_t)g * 16);
            }
            CP_COMMIT();
            CP_WAIT(1);
        } else {
            CP_WAIT(0);
        }
        __syncthreads();

        // overlapped x loads: tail-norm strip every slice; X k[128,256) at ts=0
        {
            #pragma unroll
            for (int h = 0; h < 2; ++h) {
                const int k = 256 + ts * 32 + h * 16 + wid;
                const float4 v = *(const float4*)(xb + (size_t)k * HWDIM + px4);
                a2[0] += v.x * v.x; a2[1] += v.y * v.y;
                a2[2] += v.z * v.z; a2[3] += v.w * v.w;
            }
        }
        if (ts == 0) {
            #pragma unroll 4
            for (int it = 0; it < 8; ++it) {
                const int k = 128 + wid + it * 16;
                const float4 v = *(const float4*)(xb + (size_t)k * HWDIM + px4);
                a1[0] += v.x * v.x; a1[1] += v.y * v.y;
                a1[2] += v.z * v.z; a1[3] += v.w * v.w;
                uint32_t p0 = __half_as_ushort(__float2half_rn(v.x)) |
                              ((uint32_t)__half_as_ushort(__float2half_rn(v.y)) << 16);
                uint32_t p1 = __half_as_ushort(__float2half_rn(v.z)) |
                              ((uint32_t)__half_as_ushort(__float2half_rn(v.w)) << 16);
                const uint32_t a = (uint32_t)(k << 8) +
                                   (((uint32_t)(px4 << 1)) ^ ((k & 7) << 4));
                *(uint2*)(smem + SM_X + a) = make_uint2(p0, p1);
            }
        }

        if ((ts & 1) == 0) {
            #pragma unroll
            for (int mt = 0; mt < 4; ++mt)
                #pragma unroll
                for (int nt = 0; nt < 4; ++nt)
                    d[mt][nt][0] = d[mt][nt][1] = 0u;
        }

        const uint32_t abuf = smx + SM_B + (ts & 1) * 65536;
        const uint32_t xk0  = (uint32_t)((ts & 1) * 128);

        // frag prefetch ks=0
        {
            const uint32_t brow = smx + SM_X + ((xk0 + krow) << 8);
            #pragma unroll
            for (int G = 0; G < 2; ++G)
                ldsm_x4t(fb[0][G*4+0], fb[0][G*4+1], fb[0][G*4+2], fb[0][G*4+3],
                         brow + pxoff[G]);
            #pragma unroll
            for (int mt = 0; mt < 4; ++mt)
                ldsm_x4(fa[0][mt*4+0], fa[0][mt*4+1], fa[0][mt*4+2], fa[0][mt*4+3],
                        abuf + aB0 + (uint32_t)(mt * 4096) + ((a_hi ^ fA) << 4));
        }

        #pragma unroll
        for (int ks = 0; ks < 8; ++ks) {
            const int cur = ks & 1;
            if (ks < 7) {
                const int nk = ks + 1;
                const uint32_t brow = smx + SM_X + ((xk0 + (uint32_t)(nk * 16) + krow) << 8);
                #pragma unroll
                for (int G = 0; G < 2; ++G)
                    ldsm_x4t(fb[cur^1][G*4+0], fb[cur^1][G*4+1],
                             fb[cur^1][G*4+2], fb[cur^1][G*4+3], brow + pxoff[G]);
                #pragma unroll
                for (int mt = 0; mt < 4; ++mt)
                    ldsm_x4(fa[cur^1][mt*4+0], fa[cur^1][mt*4+1],
                            fa[cur^1][mt*4+2], fa[cur^1][mt*4+3],
                            abuf + aB0 + (uint32_t)(mt * 4096) +
                            (((((uint32_t)nk << 1) | a_hi) ^ fA) << 4));
            }
            #pragma unroll
            for (int mt = 0; mt < 4; ++mt)
                #pragma unroll
                for (int nt = 0; nt < 4; ++nt)
                    mma_h(d[mt][nt][0], d[mt][nt][1],
                          fa[cur][mt*4+0], fa[cur][mt*4+1],
                          fa[cur][mt*4+2], fa[cur][mt*4+3],
                          fb[cur][(nt>>1)*4 + (nt&1)*2],
                          fb[cur][(nt>>1)*4 + (nt&1)*2 + 1]);
        }

        if ((ts & 1) == 1) {             // chunk done: pure max fold (no idx)
            #pragma unroll
            for (int nt = 0; nt < 4; ++nt)
                #pragma unroll
                for (int mt = 0; mt < 4; ++mt)
                    rmax2[nt] = hmax2u(rmax2[nt], hmax2u(d[mt][nt][0], d[mt][nt][1]));
        }
        __syncthreads();
    }

    // ---- publish norms ----
    #pragma unroll
    for (int j = 0; j < 4; ++j) {
        atomicAdd(&s_n2[px4 + j], a1[j] + a2[j]);
        atomicAdd(&s_t2[px4 + j], a2[j]);
    }

    // ---- cross-lane max (rows live on lane>>2) ----
    #pragma unroll
    for (int o = 4; o <= 16; o <<= 1)
        #pragma unroll
        for (int s = 0; s < 4; ++s)
            rmax2[s] = hmax2u(rmax2[s], __shfl_xor_sync(0xffffffffu, rmax2[s], o));
    if (lane < 4) {
        #pragma unroll
        for (int nt = 0; nt < 4; ++nt) {
            const float2 f = __half22float2(*(const __half2*)&rmax2[nt]);
            const int px = warp_n * 32 + (nt >> 1) * 16 + (nt & 1) * 8 + lane * 2;
            s_rm[warp_m * 128 + px]     = f.x;
            s_rm[warp_m * 128 + px + 1] = f.y;
        }
    }
    __syncthreads();

    // ---- per-pixel screen: dot1max + ||x2||*Bmax > 0.75*||x|| ? ----
    const float bmax = g_bmax;
    if (tid < TILE_PX) {
        float bv = s_rm[tid];
        #pragma unroll
        for (int g = 1; g < 4; ++g) bv = fmaxf(bv, s_rm[g * 128 + tid]);
        const float nx = fmaxf(sqrtf(s_n2[tid]), 1e-12f);
        const float xt = sqrtf(s_t2[tid]);
        s_flag[tid] = (bv + xt * bmax > 0.75f * nx) ? 1 : 0;
        s_pass[tid] = 0;
        s_idx[tid]  = 0;
    }
    __syncthreads();

    // ---- exact fp32 path for flagged pixels (expected: none) ----
    for (int px = 0; px < TILE_PX; ++px) {
        if (!s_flag[px]) continue;
        for (int c = tid; c < CDIM; c += THREADS)
            s_xv[c] = x[(size_t)b * CDIM * HWDIM + (size_t)c * HWDIM + n0 + px];
        if (tid == 0) { *s_bestu = 0u; *s_besti = 0x7fffffff; }
        __syncthreads();
        float lb = -3.0e38f; int li = 0x7fffffff;
        #pragma unroll 1
        for (int mm = tid * 2; mm < tid * 2 + 2; ++mm) {
            const float* mr = memory + (size_t)mm * CDIM;
            float dot = 0.f, nn = 0.f;
            for (int c = 0; c < CDIM; ++c) { const float mv = mr[c]; dot += s_xv[c] * mv; nn += mv * mv; }
            const float v = dot / fmaxf(sqrtf(nn), 1e-12f);
            if (v > lb) { lb = v; li = mm; }
        }
        unsigned enc = __float_as_uint(lb);
        enc = (enc & 0x80000000u) ? ~enc : (enc | 0x80000000u);
        atomicMax(s_bestu, enc);
        __syncthreads();
        if (enc == *s_bestu) atomicMin(s_besti, li);
        __syncthreads();
        if (tid == 0) {
            unsigned u = *s_bestu;
            const float bvf = __uint_as_float((u & 0x80000000u) ? (u & 0x7fffffffu) : ~u);
            const float nx = fmaxf(sqrtf(s_n2[px]), 1e-12f);
            s_pass[px] = (bvf > THRESH * nx) ? 1 : 0;
            s_idx[px]  = *s_besti;
        }
        __syncthreads();
    }
    __syncthreads();

    // ---- writeback: full tile, coalesced; skip gather loads when masked ----
    {
        const int pxl = tid & 127;
        const int c0  = tid >> 7;
        float* ob = out + (size_t)b * CDIM * HWDIM + n0 + pxl;
        if (s_pass[pxl]) {
            const float* mrow = memory + (size_t)s_idx[pxl] * CDIM;
            #pragma unroll 8
            for (int c = c0; c < CDIM; c += 4)
                ob[(size_t)c * HWDIM] = mrow[c];
        } else {
            #pragma unroll 8
            for (int c = c0; c < CDIM; c += 4)
                ob[(size_t)c * HWDIM] = 0.0f;
        }
    }
}

// ---------------------------------------------------------------------------
extern "C" void kernel_launch(void* const* d_in, const int* in_sizes, int n_in,
                              void* d_out, int out_size) {
    const float* x      = (const float*)d_in[0];
    const float* memory = (const float*)d_in[1];
    float* out          = (float*)d_out;

    cudaFuncSetAttribute(hardmem_main_kernel,
                         cudaFuncAttributeMaxDynamicSharedMemorySize, SM_TOTAL);

    normalize_mem_kernel<<<MMEM, 128>>>(memory);
    hardmem_main_kernel<<<32 * (HWDIM / TILE_PX), THREADS, SM_TOTAL>>>(x, memory, out);
}

// round 14
// speedup vs baseline: 1.9138x; 1.0619x over previous
#include <cuda_runtime.h>
#include <cuda_fp16.h>
#include <cstdint>

// ============================================================================
// HardMemory R14: R13 + speculative zero writeback overlapped with GEMM.
//   x: [32, 512, 64, 64] f32, memory: [1024, 512] f32, out like x.
// cos(x, m_hat) <= (dot1(x1,m1_hat) + ||x2||*Bmax)/||x||, Bmax = max ||m2_hat||.
// GEMM K=256 only; flag iff dot1max + ||x2||*Bmax > 0.75*||x|| (true 0.8).
// Flagged pixels (expected none) -> exact fp32 path (also true argmax).
// Output is zero except pass pixels -> zeros are streamed to GMEM DURING the
// mainloop (stores drain behind compute; DRAM at 22% has headroom); epilogue
// touches only pass pixels. __syncthreads orders intra-CTA global stores.
// ============================================================================

#define THRESH   0.8f
#define CDIM     512
#define KGEMM    256
#define HWDIM    4096
#define MMEM     1024
#define TILE_PX  128
#define THREADS  512

// Prepass: normalized memory rows, first 256 channels, fp16 [1024][256]
__device__ __align__(16) unsigned char g_memh[MMEM * KGEMM * 2];
__device__ float g_bmax;   // max over rows of ||m_hat[256:512]|| (zero-init)

// ---------------------------------------------------------------------------
// smem layout (bytes)
// ---------------------------------------------------------------------------
#define SM_X     0                        // [256 k][256B px-fp16] = 65536
#define SM_B     65536                    // 2 x [256 m][256B k-fp16] = 131072
#define SM_N2    196608                   // 128 f32 full ||x||^2
#define SM_T2    197120                   // 128 f32 tail ||x2||^2
#define SM_RM    197632                   // 4*128 f32
#define SM_FLAG  199680                   // 128 i32
#define SM_PASS  200192
#define SM_IDX   200704
#define SM_XV    201216                   // 512 f32
#define SM_BESTU 203264
#define SM_BESTI 203268
#define SM_TOTAL 203328

// ---------------------------------------------------------------------------
__device__ __forceinline__ uint32_t smem_u32(const void* p) {
    uint32_t a;
    asm("{ .reg .u64 t; cvta.to.shared.u64 t, %1; cvt.u32.u64 %0, t; }"
        : "=r"(a) : "l"(p));
    return a;
}
__device__ __forceinline__ void cp_async16(uint32_t dst, const void* src) {
    asm volatile("cp.async.cg.shared.global [%0], [%1], 16;"
                 :: "r"(dst), "l"(src) : "memory");
}
#define CP_COMMIT() asm volatile("cp.async.commit_group;" ::: "memory")
#define CP_WAIT(N)  asm volatile("cp.async.wait_group %0;" :: "n"(N) : "memory")

__device__ __forceinline__ void ldsm_x4(uint32_t& r0, uint32_t& r1,
                                        uint32_t& r2, uint32_t& r3, uint32_t a) {
    asm volatile("ldmatrix.sync.aligned.m8n8.x4.shared.b16 {%0,%1,%2,%3}, [%4];"
                 : "=r"(r0), "=r"(r1), "=r"(r2), "=r"(r3) : "r"(a));
}
__device__ __forceinline__ void ldsm_x4t(uint32_t& r0, uint32_t& r1,
                                         uint32_t& r2, uint32_t& r3, uint32_t a) {
    asm volatile("ldmatrix.sync.aligned.m8n8.x4.trans.shared.b16 {%0,%1,%2,%3}, [%4];"
                 : "=r"(r0), "=r"(r1), "=r"(r2), "=r"(r3) : "r"(a));
}
__device__ __forceinline__ void mma_h(uint32_t& d0, uint32_t& d1,
                                      uint32_t a0, uint32_t a1, uint32_t a2, uint32_t a3,
                                      uint32_t b0, uint32_t b1) {
    asm volatile(
        "mma.sync.aligned.m16n8k16.row.col.f16.f16.f16.f16 "
        "{%0,%1}, {%2,%3,%4,%5}, {%6,%7}, {%0,%1};"
        : "+r"(d0), "+r"(d1)
        : "r"(a0), "r"(a1), "r"(a2), "r"(a3), "r"(b0), "r"(b1));
}
__device__ __forceinline__ uint32_t hmax2u(uint32_t a, uint32_t b) {
    const __half2 r = __hmax2(*(const __half2*)&a, *(const __half2*)&b);
    return *(const uint32_t*)&r;
}

// ---------------------------------------------------------------------------
// Prepass: m_hat = memory/max(||row||,eps); store m_hat[0:256] fp16;
// atomicMax ||m_hat[256:512]|| into g_bmax (idempotent across graph replays).
// ---------------------------------------------------------------------------
__global__ __launch_bounds__(128) void normalize_mem_kernel(const float* __restrict__ memory) {
    const int m = blockIdx.x, tid = threadIdx.x;
    const float4 v = *(const float4*)(memory + (size_t)m * CDIM + tid * 4);
    float ss = v.x * v.x + v.y * v.y + v.z * v.z + v.w * v.w;
    #pragma unroll
    for (int o = 16; o > 0; o >>= 1) ss += __shfl_xor_sync(0xffffffffu, ss, o);
    __shared__ float ws[4];
    if ((tid & 31) == 0) ws[tid >> 5] = ss;
    __syncthreads();
    const float tot  = ws[0] + ws[1] + ws[2] + ws[3];
    const float tail = ws[2] + ws[3];                 // k in [256, 512)
    const float s = 1.0f / fmaxf(sqrtf(tot), 1e-12f);
    if (tid < 64) {                                   // k < 256: store fp16
        uint32_t p0 = __half_as_ushort(__float2half_rn(v.x * s)) |
                      ((uint32_t)__half_as_ushort(__float2half_rn(v.y * s)) << 16);
        uint32_t p1 = __half_as_ushort(__float2half_rn(v.z * s)) |
                      ((uint32_t)__half_as_ushort(__float2half_rn(v.w * s)) << 16);
        *(uint2*)(g_memh + (size_t)m * (KGEMM * 2) + tid * 8) = make_uint2(p0, p1);
    }
    if (tid == 0) {
        const float tn = sqrtf(tail) * s;             // ||m_hat tail|| (>= 0)
        atomicMax((unsigned*)&g_bmax, __float_as_uint(tn));
    }
}

// ---------------------------------------------------------------------------
// Main: 1024 CTAs x 512 thr. 16 warps = 4 warp_m (m64) x 4 warp_n (n32).
// Chunk = 256 mem rows (4 chunks); B slice [256 m][128 k] fp16 = 64KB, x2 buf.
// Zero output streamed during mainloop; epilogue writes pass pixels only.
// ---------------------------------------------------------------------------
__global__ __launch_bounds__(THREADS, 1) void hardmem_main_kernel(
    const float* __restrict__ x,
    const float* __restrict__ memory,
    float* __restrict__ out)
{
    extern __shared__ char smem[];
    const uint32_t smx = smem_u32(smem);
    const int tid = threadIdx.x;
    const int lane = tid & 31;
    const int wid = tid >> 5;
    const int warp_m = wid >> 2;        // 0..3 -> m64 within 256-chunk
    const int warp_n = wid & 3;         // 0..3 -> px32
    const int b  = blockIdx.x >> 5;
    const int n0 = (blockIdx.x & 31) << 7;

    float* s_n2   = (float*)(smem + SM_N2);
    float* s_t2   = (float*)(smem + SM_T2);
    float* s_rm   = (float*)(smem + SM_RM);
    int*   s_flag = (int*)(smem + SM_FLAG);
    int*   s_pass = (int*)(smem + SM_PASS);
    int*   s_idx  = (int*)(smem + SM_IDX);
    float* s_xv   = (float*)(smem + SM_XV);
    unsigned* s_bestu = (unsigned*)(smem + SM_BESTU);
    int*      s_besti = (int*)(smem + SM_BESTI);

    if (tid < TILE_PX) { s_n2[tid] = 0.0f; s_t2[tid] = 0.0f; }

    const float* xb = x + (size_t)b * CDIM * HWDIM + n0;
    float* ob0 = out + (size_t)b * CDIM * HWDIM + n0;
    const int px4 = lane << 2;                 // 4 fixed pixels per lane
    float a1[4] = {0.f, 0.f, 0.f, 0.f};        // head ||x1||^2 partials
    float a2[4] = {0.f, 0.f, 0.f, 0.f};        // tail ||x2||^2 partials

    // ---- prefetch B slice 0 (chunk 0, k 0..127): 256 rows x 256B = 64KB ----
    {
        #pragma unroll
        for (int i = 0; i < 8; ++i) {
            const int j = tid + i * THREADS;          // 4096 granules of 16B
            const int m = j >> 4, g = j & 15;
            cp_async16(smx + SM_B + m * 256 + (((uint32_t)g ^ (uint32_t)(m & 7)) << 4),
                       g_memh + (size_t)m * 512 + (size_t)g * 16);
        }
        CP_COMMIT();
    }

    // ---- serial head: X k in [0,128) only (rest overlapped in mainloop) ----
    {
        #pragma unroll 4
        for (int it = 0; it < 8; ++it) {
            const int k = wid + it * 16;
            const float4 v = *(const float4*)(xb + (size_t)k * HWDIM + px4);
            a1[0] += v.x * v.x; a1[1] += v.y * v.y;
            a1[2] += v.z * v.z; a1[3] += v.w * v.w;
            uint32_t p0 = __half_as_ushort(__float2half_rn(v.x)) |
                          ((uint32_t)__half_as_ushort(__float2half_rn(v.y)) << 16);
            uint32_t p1 = __half_as_ushort(__float2half_rn(v.z)) |
                          ((uint32_t)__half_as_ushort(__float2half_rn(v.w)) << 16);
            const uint32_t a = (uint32_t)(k << 8) + (((uint32_t)(px4 << 1)) ^ ((k & 7) << 4));
            *(uint2*)(smem + SM_X + a) = make_uint2(p0, p1);
        }
    }

    // ---- lane addressing ----
    const int lr = lane & 7;
    const int lh = (lane >> 3) & 1;
    const int lq = (lane >> 4) & 1;
    const uint32_t a_hi = (uint32_t)(lane >> 4);
    const uint32_t aB0 = (uint32_t)((warp_m * 64 + (lane & 15)) << 8);  // *256B
    const uint32_t fA  = (uint32_t)lr;
    const uint32_t krow = (uint32_t)(lr + lh * 8);
    uint32_t pxoff[2];
    #pragma unroll
    for (int G = 0; G < 2; ++G)
        pxoff[G] = ((uint32_t)((warp_n * 32 + lq * 8 + G * 16) << 1)) ^ ((uint32_t)lr << 4);

    uint32_t rmax2[4];
    {
        const __half2 ninf = __float2half2_rn(-60000.0f);
        #pragma unroll
        for (int s = 0; s < 4; ++s) rmax2[s] = *(const uint32_t*)&ninf;
    }
    uint32_t d[4][4][2];                 // [mt][nt][reg] fp16x2 accum (32 regs)
    uint32_t fa[2][16], fb[2][8];        // double-buffered frags (48 regs)

    // ---- mainloop: 8 slices = 4 chunks x 2 k-slices of 128 ----
    #pragma unroll 1
    for (int ts = 0; ts < 8; ++ts) {
        if (ts + 1 < 8) {
            const int nx2 = ts + 1;
            const unsigned char* src = g_memh +
                (size_t)(nx2 >> 1) * (256 * 512) + (size_t)(nx2 & 1) * 256;
            const uint32_t dstb = smx + SM_B + (nx2 & 1) * 65536;
            #pragma unroll
            for (int i = 0; i < 8; ++i) {
                const int j = tid + i * THREADS;
                const int m = j >> 4, g = j & 15;
                cp_async16(dstb + m * 256 + (((uint32_t)g ^ (uint32_t)(m & 7)) << 4),
                           src + (size_t)m * 512 + (size_t)g * 16);
            }
            CP_COMMIT();
            CP_WAIT(1);
        } else {
            CP_WAIT(0);
        }
        __syncthreads();

        // overlapped x tail-norm strip (k >= 256) + speculative zero writeback
        {
            #pragma unroll
            for (int h = 0; h < 2; ++h) {
                const int k = 256 + ts * 32 + h * 16 + wid;
                const float4 v = *(const float4*)(xb + (size_t)k * HWDIM + px4);
                a2[0] += v.x * v.x; a2[1] += v.y * v.y;
                a2[2] += v.z * v.z; a2[3] += v.w * v.w;
            }
            // 4 float4 zero-stores per thread per slice = full 256KB over 8 slices
            const float4 z = make_float4(0.f, 0.f, 0.f, 0.f);
            #pragma unroll
            for (int i = 0; i < 4; ++i) {
                const int j2 = ts * 2048 + i * THREADS + tid;  // 0..16383
                const int c = j2 >> 5, gg = j2 & 31;
                *(float4*)(ob0 + (size_t)c * HWDIM + gg * 4) = z;
            }
        }
        if (ts == 0) {
            #pragma unroll 4
            for (int it = 0; it < 8; ++it) {
                const int k = 128 + wid + it * 16;
                const float4 v = *(const float4*)(xb + (size_t)k * HWDIM + px4);
                a1[0] += v.x * v.x; a1[1] += v.y * v.y;
                a1[2] += v.z * v.z; a1[3] += v.w * v.w;
                uint32_t p0 = __half_as_ushort(__float2half_rn(v.x)) |
                              ((uint32_t)__half_as_ushort(__float2half_rn(v.y)) << 16);
                uint32_t p1 = __half_as_ushort(__float2half_rn(v.z)) |
                              ((uint32_t)__half_as_ushort(__float2half_rn(v.w)) << 16);
                const uint32_t a = (uint32_t)(k << 8) +
                                   (((uint32_t)(px4 << 1)) ^ ((k & 7) << 4));
                *(uint2*)(smem + SM_X + a) = make_uint2(p0, p1);
            }
        }

        if ((ts & 1) == 0) {
            #pragma unroll
            for (int mt = 0; mt < 4; ++mt)
                #pragma unroll
                for (int nt = 0; nt < 4; ++nt)
                    d[mt][nt][0] = d[mt][nt][1] = 0u;
        }

        const uint32_t abuf = smx + SM_B + (ts & 1) * 65536;
        const uint32_t xk0  = (uint32_t)((ts & 1) * 128);

        // frag prefetch ks=0
        {
            const uint32_t brow = smx + SM_X + ((xk0 + krow) << 8);
            #pragma unroll
            for (int G = 0; G < 2; ++G)
                ldsm_x4t(fb[0][G*4+0], fb[0][G*4+1], fb[0][G*4+2], fb[0][G*4+3],
                         brow + pxoff[G]);
            #pragma unroll
            for (int mt = 0; mt < 4; ++mt)
                ldsm_x4(fa[0][mt*4+0], fa[0][mt*4+1], fa[0][mt*4+2], fa[0][mt*4+3],
                        abuf + aB0 + (uint32_t)(mt * 4096) + ((a_hi ^ fA) << 4));
        }

        #pragma unroll
        for (int ks = 0; ks < 8; ++ks) {
            const int cur = ks & 1;
            if (ks < 7) {
                const int nk = ks + 1;
                const uint32_t brow = smx + SM_X + ((xk0 + (uint32_t)(nk * 16) + krow) << 8);
                #pragma unroll
                for (int G = 0; G < 2; ++G)
                    ldsm_x4t(fb[cur^1][G*4+0], fb[cur^1][G*4+1],
                             fb[cur^1][G*4+2], fb[cur^1][G*4+3], brow + pxoff[G]);
                #pragma unroll
                for (int mt = 0; mt < 4; ++mt)
                    ldsm_x4(fa[cur^1][mt*4+0], fa[cur^1][mt*4+1],
                            fa[cur^1][mt*4+2], fa[cur^1][mt*4+3],
                            abuf + aB0 + (uint32_t)(mt * 4096) +
                            (((((uint32_t)nk << 1) | a_hi) ^ fA) << 4));
            }
            #pragma unroll
            for (int mt = 0; mt < 4; ++mt)
                #pragma unroll
                for (int nt = 0; nt < 4; ++nt)
                    mma_h(d[mt][nt][0], d[mt][nt][1],
                          fa[cur][mt*4+0], fa[cur][mt*4+1],
                          fa[cur][mt*4+2], fa[cur][mt*4+3],
                          fb[cur][(nt>>1)*4 + (nt&1)*2],
                          fb[cur][(nt>>1)*4 + (nt&1)*2 + 1]);
        }

        if ((ts & 1) == 1) {             // chunk done: pure max fold (no idx)
            #pragma unroll
            for (int nt = 0; nt < 4; ++nt)
                #pragma unroll
                for (int mt = 0; mt < 4; ++mt)
                    rmax2[nt] = hmax2u(rmax2[nt], hmax2u(d[mt][nt][0], d[mt][nt][1]));
        }
        __syncthreads();
    }

    // ---- publish norms ----
    #pragma unroll
    for (int j = 0; j < 4; ++j) {
        atomicAdd(&s_n2[px4 + j], a1[j] + a2[j]);
        atomicAdd(&s_t2[px4 + j], a2[j]);
    }

    // ---- cross-lane max (rows live on lane>>2) ----
    #pragma unroll
    for (int o = 4; o <= 16; o <<= 1)
        #pragma unroll
        for (int s = 0; s < 4; ++s)
            rmax2[s] = hmax2u(rmax2[s], __shfl_xor_sync(0xffffffffu, rmax2[s], o));
    if (lane < 4) {
        #pragma unroll
        for (int nt = 0; nt < 4; ++nt) {
            const float2 f = __half22float2(*(const __half2*)&rmax2[nt]);
            const int px = warp_n * 32 + (nt >> 1) * 16 + (nt & 1) * 8 + lane * 2;
            s_rm[warp_m * 128 + px]     = f.x;
            s_rm[warp_m * 128 + px + 1] = f.y;
        }
    }
    __syncthreads();

    // ---- per-pixel screen: dot1max + ||x2||*Bmax > 0.75*||x|| ? ----
    const float bmax = g_bmax;
    if (tid < TILE_PX) {
        float bv = s_rm[tid];
        #pragma unroll
        for (int g = 1; g < 4; ++g) bv = fmaxf(bv, s_rm[g * 128 + tid]);
        const float nx = fmaxf(sqrtf(s_n2[tid]), 1e-12f);
        const float xt = sqrtf(s_t2[tid]);
        s_flag[tid] = (bv + xt * bmax > 0.75f * nx) ? 1 : 0;
        s_pass[tid] = 0;
        s_idx[tid]  = 0;
    }
    __syncthreads();

    // ---- exact fp32 path for flagged pixels (expected: none) ----
    for (int px = 0; px < TILE_PX; ++px) {
        if (!s_flag[px]) continue;
        for (int c = tid; c < CDIM; c += THREADS)
            s_xv[c] = x[(size_t)b * CDIM * HWDIM + (size_t)c * HWDIM + n0 + px];
        if (tid == 0) { *s_bestu = 0u; *s_besti = 0x7fffffff; }
        __syncthreads();
        float lb = -3.0e38f; int li = 0x7fffffff;
        #pragma unroll 1
        for (int mm = tid * 2; mm < tid * 2 + 2; ++mm) {
            const float* mr = memory + (size_t)mm * CDIM;
            float dot = 0.f, nn = 0.f;
            for (int c = 0; c < CDIM; ++c) { const float mv = mr[c]; dot += s_xv[c] * mv; nn += mv * mv; }
            const float v = dot / fmaxf(sqrtf(nn), 1e-12f);
            if (v > lb) { lb = v; li = mm; }
        }
        unsigned enc = __float_as_uint(lb);
        enc = (enc & 0x80000000u) ? ~enc : (enc | 0x80000000u);
        atomicMax(s_bestu, enc);
        __syncthreads();
        if (enc == *s_bestu) atomicMin(s_besti, li);
        __syncthreads();
        if (tid == 0) {
            unsigned u = *s_bestu;
            const float bvf = __uint_as_float((u & 0x80000000u) ? (u & 0x7fffffffu) : ~u);
            const float nx = fmaxf(sqrtf(s_n2[px]), 1e-12f);
            s_pass[px] = (bvf > THRESH * nx) ? 1 : 0;
            s_idx[px]  = *s_besti;
        }
        __syncthreads();
    }
    __syncthreads();

    // ---- pass pixels only (zeros already streamed during mainloop) ----
    {
        const int pxl = tid & 127;
        if (s_pass[pxl]) {
            const int c0 = tid >> 7;
            const float* mrow = memory + (size_t)s_idx[pxl] * CDIM;
            float* ob = ob0 + pxl;
            #pragma unroll 8
            for (int c = c0; c < CDIM; c += 4)
                ob[(size_t)c * HWDIM] = mrow[c];
        }
    }
}

// ---------------------------------------------------------------------------
extern "C" void kernel_launch(void* const* d_in, const int* in_sizes, int n_in,
                              void* d_out, int out_size) {
    const float* x      = (const float*)d_in[0];
    const float* memory = (const float*)d_in[1];
    float* out          = (float*)d_out;

    cudaFuncSetAttribute(hardmem_main_kernel,
                         cudaFuncAttributeMaxDynamicSharedMemorySize, SM_TOTAL);

    normalize_mem_kernel<<<MMEM, 128>>>(memory);
    hardmem_main_kernel<<<32 * (HWDIM / TILE_PX), THREADS, SM_TOTAL>>>(x, memory, out);
}